// round 3
// baseline (speedup 1.0000x reference)
#include <cuda_runtime.h>
#include <cuda_bf16.h>
#include <math.h>

#define N_ANCH 49104
#define NCLS   90
#define NB     8
#define KRET   100
#define SCORE_THR 0.3f
#define IOU_THR   0.45f
#define THR_HI 0.98f
#define CAP    2048
#define MCAP   4096
#define TOT    (NB * N_ANCH * NCLS)
#define TOT4   (TOT / 4)

typedef unsigned long long ull;

// ---------------- device scratch ----------------
__device__ float g_boxes[NB * N_ANCH * 4];
__device__ int   g_cnt[NB * NCLS];
__device__ ull   g_cand[(size_t)NB * NCLS * CAP];
__device__ float g_cls_scores[NB * NCLS * KRET];
__device__ float g_cls_boxes[NB * NCLS * KRET * 4];

// ---------------- kernel 1: decode + clip (+ zero counters) ----------------
__global__ void decode_kernel(const float* __restrict__ bboxes,
                              const float* __restrict__ anchors) {
    int idx = blockIdx.x * blockDim.x + threadIdx.x;
    if (idx < NB * NCLS) g_cnt[idx] = 0;
    if (idx >= NB * N_ANCH) return;
    int n = idx % N_ANCH;
    float4 d = ((const float4*)bboxes)[idx];
    float4 a = ((const float4*)anchors)[n];
    float aw = a.z - a.x, ah = a.w - a.y;
    float acx = a.x + 0.5f * aw, acy = a.y + 0.5f * ah;
    float dx = d.x * 0.1f, dy = d.y * 0.1f;
    float dw = fminf(d.z * 0.2f, 4.135f);
    float dh = fminf(d.w * 0.2f, 4.135f);
    float cx = acx + dx * aw, cy = acy + dy * ah;
    float w = aw * expf(dw), h = ah * expf(dh);
    float4 o;
    o.x = fminf(fmaxf(cx - 0.5f * w, 0.0f), 512.0f);
    o.y = fminf(fmaxf(cy - 0.5f * h, 0.0f), 512.0f);
    o.z = fminf(fmaxf(cx + 0.5f * w, 0.0f), 512.0f);
    o.w = fminf(fmaxf(cy + 0.5f * h, 0.0f), 512.0f);
    ((float4*)g_boxes)[idx] = o;
}

// ---------------- kernel 2: single streaming pass, append high candidates ----
__device__ __forceinline__ void try_append(float s, unsigned flat) {
    if (s > THR_HI) {
        unsigned rem = flat % (unsigned)(N_ANCH * NCLS);
        int b = flat / (unsigned)(N_ANCH * NCLS);
        int n = rem / NCLS;
        int c = rem % NCLS;
        int bc = b * NCLS + c;
        int pos = atomicAdd(&g_cnt[bc], 1);
        if (pos < CAP)
            g_cand[(size_t)bc * CAP + pos] =
                ((ull)__float_as_uint(s) << 32) | (unsigned)(~(unsigned)n);
    }
}

__global__ void scan_kernel(const float* __restrict__ scores) {
    unsigned i4 = blockIdx.x * blockDim.x + threadIdx.x;
    if (i4 >= TOT4) return;
    float4 v = ((const float4*)scores)[i4];
    unsigned base = i4 * 4u;
    try_append(v.x, base + 0u);
    try_append(v.y, base + 1u);
    try_append(v.z, base + 2u);
    try_append(v.w, base + 3u);
}

// descending bitonic sort on shared ull keys, P power of two
__device__ void bitonic_desc(ull* k, int P) {
    for (int len = 2; len <= P; len <<= 1) {
        for (int j = len >> 1; j > 0; j >>= 1) {
            __syncthreads();
            for (int i = threadIdx.x; i < P; i += blockDim.x) {
                int ixj = i ^ j;
                if (ixj > i) {
                    bool desc = ((i & len) == 0);
                    ull x = k[i], y = k[ixj];
                    if (desc ? (x < y) : (x > y)) { k[i] = y; k[ixj] = x; }
                }
            }
        }
    }
    __syncthreads();
}

// ---------------- kernel 3: per-(b,c) top-100 + greedy NMS ----------------
__global__ void topk_nms_kernel(const float* __restrict__ scores) {
    int c = blockIdx.x, b = blockIdx.y;
    int bc = b * NCLS + c;

    __shared__ ull keys[CAP];
    __shared__ int s_cnt, s_edge;
    __shared__ unsigned hist[512];
    __shared__ float bx[KRET][4];
    __shared__ float vv[KRET];
    __shared__ unsigned char supp[KRET], keepf[KRET];

    int cnt = g_cnt[bc];
    if (cnt > CAP) cnt = CAP;
    for (int i = threadIdx.x; i < cnt; i += blockDim.x)
        keys[i] = g_cand[(size_t)bc * CAP + i];
    if (threadIdx.x == 0) s_cnt = cnt;
    __syncthreads();

    if (cnt < KRET) {
        // fallback (rare/never): gather more candidates from (0.3, 0.98]
        for (int i = threadIdx.x; i < 512; i += blockDim.x) hist[i] = 0;
        __syncthreads();
        const float invw = 512.0f / (THR_HI - SCORE_THR);
        for (int n = threadIdx.x; n < N_ANCH; n += blockDim.x) {
            float s = scores[((size_t)b * N_ANCH + n) * NCLS + c];
            if (s > SCORE_THR && s <= THR_HI) {
                int bin = (int)((s - SCORE_THR) * invw);
                if (bin > 511) bin = 511;
                atomicAdd(&hist[bin], 1u);
            }
        }
        __syncthreads();
        if (threadIdx.x == 0) {
            int need = KRET - cnt;
            unsigned cum = 0; int edge = 0;
            for (int e = 511; e >= 0; --e) {
                cum += hist[e];
                if ((int)cum >= need) { edge = e; break; }
            }
            s_edge = edge;
        }
        __syncthreads();
        int edge = s_edge;
        for (int n = threadIdx.x; n < N_ANCH; n += blockDim.x) {
            float s = scores[((size_t)b * N_ANCH + n) * NCLS + c];
            if (s > SCORE_THR && s <= THR_HI) {
                int bin = (int)((s - SCORE_THR) * invw);
                if (bin > 511) bin = 511;
                if (bin >= edge) {
                    int pos = atomicAdd(&s_cnt, 1);
                    if (pos < CAP)
                        keys[pos] = ((ull)__float_as_uint(s) << 32) |
                                    (unsigned)(~(unsigned)n);
                }
            }
        }
        __syncthreads();
    }

    int M = s_cnt < CAP ? s_cnt : CAP;
    int P = 128; while (P < M) P <<= 1;
    for (int i = threadIdx.x; i < P; i += blockDim.x)
        if (i >= M) keys[i] = 0ull;
    bitonic_desc(keys, P);

    if (threadIdx.x < KRET) {
        int k = threadIdx.x;
        if (k < M) {
            ull key = keys[k];
            float s = __uint_as_float((unsigned)(key >> 32));
            unsigned idx = ~(unsigned)(key & 0xFFFFFFFFull);
            vv[k] = s;
            const float4 bp = ((const float4*)g_boxes)[(size_t)b * N_ANCH + idx];
            bx[k][0] = bp.x; bx[k][1] = bp.y; bx[k][2] = bp.z; bx[k][3] = bp.w;
        } else {
            vv[k] = -1.0f;
            bx[k][0] = bx[k][1] = bx[k][2] = bx[k][3] = 0.0f;
        }
        supp[k] = 0; keepf[k] = 0;
    }
    __syncthreads();

    // greedy NMS, matches jax scan order
    for (int i = 0; i < KRET; ++i) {
        bool keep_i = (!supp[i]) && (vv[i] > 0.0f);
        if (threadIdx.x == 0) keepf[i] = keep_i ? 1 : 0;
        int j = threadIdx.x;
        if (keep_i && j < KRET && j != i) {
            float xx1 = fmaxf(bx[i][0], bx[j][0]);
            float yy1 = fmaxf(bx[i][1], bx[j][1]);
            float xx2 = fminf(bx[i][2], bx[j][2]);
            float yy2 = fminf(bx[i][3], bx[j][3]);
            float w = fmaxf(xx2 - xx1, 0.0f);
            float h = fmaxf(yy2 - yy1, 0.0f);
            float inter = w * h;
            float ai = (bx[i][2] - bx[i][0]) * (bx[i][3] - bx[i][1]);
            float aj = (bx[j][2] - bx[j][0]) * (bx[j][3] - bx[j][1]);
            float iou = inter / (ai + aj - inter + 1e-8f);
            if (iou > IOU_THR) supp[j] = 1;
        }
        __syncthreads();
    }

    if (threadIdx.x < KRET) {
        int k = threadIdx.x;
        int base = bc * KRET + k;
        g_cls_scores[base] = keepf[k] ? vv[k] : -1.0f;
        g_cls_boxes[base * 4 + 0] = bx[k][0];
        g_cls_boxes[base * 4 + 1] = bx[k][1];
        g_cls_boxes[base * 4 + 2] = bx[k][2];
        g_cls_boxes[base * 4 + 3] = bx[k][3];
    }
}

// ---------------- kernel 4: merge via histogram selection ----------------
__global__ void merge_kernel(float* __restrict__ out) {
    __shared__ unsigned hist[513];   // bin 0 = catch-all (0, 0.98]
    __shared__ ull mkeys[MCAP];
    __shared__ int s_cnt, s_edge;
    const int M = NCLS * KRET;       // 9000
    int b = blockIdx.x;

    for (int i = threadIdx.x; i < 513; i += blockDim.x) hist[i] = 0;
    if (threadIdx.x == 0) s_cnt = 0;
    __syncthreads();

    const float invw = 512.0f / (1.0f - THR_HI);
    for (int i = threadIdx.x; i < M; i += blockDim.x) {
        float s = g_cls_scores[b * M + i];
        if (s > 0.0f) {
            int bin = (s > THR_HI) ? 1 + min(511, (int)((s - THR_HI) * invw)) : 0;
            atomicAdd(&hist[bin], 1u);
        }
    }
    __syncthreads();

    if (threadIdx.x == 0) {
        unsigned cum = 0; int edge = 0;
        for (int e = 512; e >= 0; --e) {
            cum += hist[e];
            if (cum >= KRET) { edge = e; break; }
        }
        s_edge = edge;
    }
    __syncthreads();
    int edge = s_edge;

    for (int i = threadIdx.x; i < M; i += blockDim.x) {
        float s = g_cls_scores[b * M + i];
        if (s > 0.0f) {
            int bin = (s > THR_HI) ? 1 + min(511, (int)((s - THR_HI) * invw)) : 0;
            if (bin >= edge) {
                int pos = atomicAdd(&s_cnt, 1);
                if (pos < MCAP)
                    mkeys[pos] = ((ull)__float_as_uint(s) << 32) |
                                 (unsigned)(~(unsigned)i);
            }
        }
    }
    __syncthreads();

    int cnt = s_cnt < MCAP ? s_cnt : MCAP;
    int P = 128; while (P < cnt) P <<= 1;
    for (int i = threadIdx.x; i < P; i += blockDim.x)
        if (i >= cnt) mkeys[i] = 0ull;
    bitonic_desc(mkeys, P);

    if (threadIdx.x < KRET) {
        int k = threadIdx.x;
        bool valid = (k < cnt);
        float b0 = 0.f, b1 = 0.f, b2 = 0.f, b3 = 0.f;
        float lab = -1.0f, sout = 0.0f;
        if (valid) {
            ull key = mkeys[k];
            float s = __uint_as_float((unsigned)(key >> 32));
            unsigned flat = ~(unsigned)(key & 0xFFFFFFFFull);
            if (s > 0.0f && flat < (unsigned)M) {
                int c = flat / KRET, kk = flat % KRET;
                int base = ((b * NCLS + c) * KRET + kk) * 4;
                b0 = g_cls_boxes[base + 0]; b1 = g_cls_boxes[base + 1];
                b2 = g_cls_boxes[base + 2]; b3 = g_cls_boxes[base + 3];
                lab = (float)c; sout = s;
            }
        }
        int bo = (b * KRET + k) * 4;
        out[bo + 0] = b0; out[bo + 1] = b1; out[bo + 2] = b2; out[bo + 3] = b3;
        out[NB * KRET * 4 + b * KRET + k] = sout;
        out[NB * KRET * 5 + b * KRET + k] = lab;
    }
}

extern "C" void kernel_launch(void* const* d_in, const int* in_sizes, int n_in,
                              void* d_out, int out_size) {
    const float* bboxes  = (const float*)d_in[0];
    const float* scores  = (const float*)d_in[1];
    const float* anchors = (const float*)d_in[2];
    float* out = (float*)d_out;

    decode_kernel<<<(NB * N_ANCH + 255) / 256, 256>>>(bboxes, anchors);
    scan_kernel<<<(TOT4 + 255) / 256, 256>>>(scores);
    topk_nms_kernel<<<dim3(NCLS, NB), 256>>>(scores);
    merge_kernel<<<NB, 512>>>(out);
}

// round 4
// speedup vs baseline: 1.0018x; 1.0018x over previous
#include <cuda_runtime.h>
#include <cuda_bf16.h>
#include <math.h>

#define N_ANCH 49104
#define NCLS   90
#define NB     8
#define KRET   100
#define SCORE_THR 0.3f
#define IOU_THR   0.45f
#define THR_HI 0.98f
#define CAP    2048
#define MCAP   4096
#define TOT    (NB * N_ANCH * NCLS)
#define TOT4   (TOT / 4)

typedef unsigned long long ull;

// ---------------- device scratch ----------------
__device__ float g_boxes[NB * N_ANCH * 4];
__device__ int   g_cnt[NB * NCLS];
__device__ ull   g_cand[(size_t)NB * NCLS * CAP];
__device__ float g_cls_scores[NB * NCLS * KRET];
__device__ float g_cls_boxes[NB * NCLS * KRET * 4];

// ---------------- kernel 1: decode + clip (+ zero counters) ----------------
__global__ void decode_kernel(const float* __restrict__ bboxes,
                              const float* __restrict__ anchors) {
    int idx = blockIdx.x * blockDim.x + threadIdx.x;
    if (idx < NB * NCLS) g_cnt[idx] = 0;
    if (idx >= NB * N_ANCH) return;
    int n = idx % N_ANCH;
    float4 d = ((const float4*)bboxes)[idx];
    float4 a = ((const float4*)anchors)[n];
    float aw = a.z - a.x, ah = a.w - a.y;
    float acx = a.x + 0.5f * aw, acy = a.y + 0.5f * ah;
    float dx = d.x * 0.1f, dy = d.y * 0.1f;
    float dw = fminf(d.z * 0.2f, 4.135f);
    float dh = fminf(d.w * 0.2f, 4.135f);
    float cx = acx + dx * aw, cy = acy + dy * ah;
    float w = aw * expf(dw), h = ah * expf(dh);
    float4 o;
    o.x = fminf(fmaxf(cx - 0.5f * w, 0.0f), 512.0f);
    o.y = fminf(fmaxf(cy - 0.5f * h, 0.0f), 512.0f);
    o.z = fminf(fmaxf(cx + 0.5f * w, 0.0f), 512.0f);
    o.w = fminf(fmaxf(cy + 0.5f * h, 0.0f), 512.0f);
    ((float4*)g_boxes)[idx] = o;
}

// ---------------- kernel 2: single streaming pass, append high candidates ----
__device__ __forceinline__ void try_append(float s, unsigned flat) {
    if (s > THR_HI) {
        unsigned rem = flat % (unsigned)(N_ANCH * NCLS);
        int b = flat / (unsigned)(N_ANCH * NCLS);
        int n = rem / NCLS;
        int c = rem % NCLS;
        int bc = b * NCLS + c;
        int pos = atomicAdd(&g_cnt[bc], 1);
        if (pos < CAP)
            g_cand[(size_t)bc * CAP + pos] =
                ((ull)__float_as_uint(s) << 32) | (unsigned)(~(unsigned)n);
    }
}

__global__ void scan_kernel(const float* __restrict__ scores) {
    unsigned i4 = blockIdx.x * blockDim.x + threadIdx.x;
    if (i4 >= TOT4) return;
    float4 v = ((const float4*)scores)[i4];
    unsigned base = i4 * 4u;
    try_append(v.x, base + 0u);
    try_append(v.y, base + 1u);
    try_append(v.z, base + 2u);
    try_append(v.w, base + 3u);
}

// descending bitonic sort on shared ull keys, P power of two
__device__ void bitonic_desc(ull* k, int P) {
    for (int len = 2; len <= P; len <<= 1) {
        for (int j = len >> 1; j > 0; j >>= 1) {
            __syncthreads();
            for (int i = threadIdx.x; i < P; i += blockDim.x) {
                int ixj = i ^ j;
                if (ixj > i) {
                    bool desc = ((i & len) == 0);
                    ull x = k[i], y = k[ixj];
                    if (desc ? (x < y) : (x > y)) { k[i] = y; k[ixj] = x; }
                }
            }
        }
    }
    __syncthreads();
}

// ---------------- kernel 3: per-(b,c) top-100 + greedy NMS ----------------
__global__ void topk_nms_kernel(const float* __restrict__ scores) {
    int c = blockIdx.x, b = blockIdx.y;
    int bc = b * NCLS + c;

    __shared__ ull keys[CAP];
    __shared__ int s_cnt, s_edge;
    __shared__ unsigned hist[512];
    __shared__ float bx[KRET][4];
    __shared__ float vv[KRET];
    __shared__ unsigned char supp[KRET], keepf[KRET];

    int cnt = g_cnt[bc];
    if (cnt > CAP) cnt = CAP;
    for (int i = threadIdx.x; i < cnt; i += blockDim.x)
        keys[i] = g_cand[(size_t)bc * CAP + i];
    if (threadIdx.x == 0) s_cnt = cnt;
    __syncthreads();

    if (cnt < KRET) {
        // fallback (rare/never): gather more candidates from (0.3, 0.98]
        for (int i = threadIdx.x; i < 512; i += blockDim.x) hist[i] = 0;
        __syncthreads();
        const float invw = 512.0f / (THR_HI - SCORE_THR);
        for (int n = threadIdx.x; n < N_ANCH; n += blockDim.x) {
            float s = scores[((size_t)b * N_ANCH + n) * NCLS + c];
            if (s > SCORE_THR && s <= THR_HI) {
                int bin = (int)((s - SCORE_THR) * invw);
                if (bin > 511) bin = 511;
                atomicAdd(&hist[bin], 1u);
            }
        }
        __syncthreads();
        if (threadIdx.x == 0) {
            int need = KRET - cnt;
            unsigned cum = 0; int edge = 0;
            for (int e = 511; e >= 0; --e) {
                cum += hist[e];
                if ((int)cum >= need) { edge = e; break; }
            }
            s_edge = edge;
        }
        __syncthreads();
        int edge = s_edge;
        for (int n = threadIdx.x; n < N_ANCH; n += blockDim.x) {
            float s = scores[((size_t)b * N_ANCH + n) * NCLS + c];
            if (s > SCORE_THR && s <= THR_HI) {
                int bin = (int)((s - SCORE_THR) * invw);
                if (bin > 511) bin = 511;
                if (bin >= edge) {
                    int pos = atomicAdd(&s_cnt, 1);
                    if (pos < CAP)
                        keys[pos] = ((ull)__float_as_uint(s) << 32) |
                                    (unsigned)(~(unsigned)n);
                }
            }
        }
        __syncthreads();
    }

    int M = s_cnt < CAP ? s_cnt : CAP;
    int P = 128; while (P < M) P <<= 1;
    for (int i = threadIdx.x; i < P; i += blockDim.x)
        if (i >= M) keys[i] = 0ull;
    bitonic_desc(keys, P);

    if (threadIdx.x < KRET) {
        int k = threadIdx.x;
        if (k < M) {
            ull key = keys[k];
            float s = __uint_as_float((unsigned)(key >> 32));
            unsigned idx = ~(unsigned)(key & 0xFFFFFFFFull);
            vv[k] = s;
            const float4 bp = ((const float4*)g_boxes)[(size_t)b * N_ANCH + idx];
            bx[k][0] = bp.x; bx[k][1] = bp.y; bx[k][2] = bp.z; bx[k][3] = bp.w;
        } else {
            vv[k] = -1.0f;
            bx[k][0] = bx[k][1] = bx[k][2] = bx[k][3] = 0.0f;
        }
        supp[k] = 0; keepf[k] = 0;
    }
    __syncthreads();

    // greedy NMS, matches jax scan order
    for (int i = 0; i < KRET; ++i) {
        bool keep_i = (!supp[i]) && (vv[i] > 0.0f);
        if (threadIdx.x == 0) keepf[i] = keep_i ? 1 : 0;
        int j = threadIdx.x;
        if (keep_i && j < KRET && j != i) {
            float xx1 = fmaxf(bx[i][0], bx[j][0]);
            float yy1 = fmaxf(bx[i][1], bx[j][1]);
            float xx2 = fminf(bx[i][2], bx[j][2]);
            float yy2 = fminf(bx[i][3], bx[j][3]);
            float w = fmaxf(xx2 - xx1, 0.0f);
            float h = fmaxf(yy2 - yy1, 0.0f);
            float inter = w * h;
            float ai = (bx[i][2] - bx[i][0]) * (bx[i][3] - bx[i][1]);
            float aj = (bx[j][2] - bx[j][0]) * (bx[j][3] - bx[j][1]);
            float iou = inter / (ai + aj - inter + 1e-8f);
            if (iou > IOU_THR) supp[j] = 1;
        }
        __syncthreads();
    }

    if (threadIdx.x < KRET) {
        int k = threadIdx.x;
        int base = bc * KRET + k;
        g_cls_scores[base] = keepf[k] ? vv[k] : -1.0f;
        g_cls_boxes[base * 4 + 0] = bx[k][0];
        g_cls_boxes[base * 4 + 1] = bx[k][1];
        g_cls_boxes[base * 4 + 2] = bx[k][2];
        g_cls_boxes[base * 4 + 3] = bx[k][3];
    }
}

// ---------------- kernel 4: merge via histogram selection ----------------
__global__ void merge_kernel(float* __restrict__ out) {
    __shared__ unsigned hist[513];   // bin 0 = catch-all (0, 0.98]
    __shared__ ull mkeys[MCAP];
    __shared__ int s_cnt, s_edge;
    const int M = NCLS * KRET;       // 9000
    int b = blockIdx.x;

    for (int i = threadIdx.x; i < 513; i += blockDim.x) hist[i] = 0;
    if (threadIdx.x == 0) s_cnt = 0;
    __syncthreads();

    const float invw = 512.0f / (1.0f - THR_HI);
    for (int i = threadIdx.x; i < M; i += blockDim.x) {
        float s = g_cls_scores[b * M + i];
        if (s > 0.0f) {
            int bin = (s > THR_HI) ? 1 + min(511, (int)((s - THR_HI) * invw)) : 0;
            atomicAdd(&hist[bin], 1u);
        }
    }
    __syncthreads();

    if (threadIdx.x == 0) {
        unsigned cum = 0; int edge = 0;
        for (int e = 512; e >= 0; --e) {
            cum += hist[e];
            if (cum >= KRET) { edge = e; break; }
        }
        s_edge = edge;
    }
    __syncthreads();
    int edge = s_edge;

    for (int i = threadIdx.x; i < M; i += blockDim.x) {
        float s = g_cls_scores[b * M + i];
        if (s > 0.0f) {
            int bin = (s > THR_HI) ? 1 + min(511, (int)((s - THR_HI) * invw)) : 0;
            if (bin >= edge) {
                int pos = atomicAdd(&s_cnt, 1);
                if (pos < MCAP)
                    mkeys[pos] = ((ull)__float_as_uint(s) << 32) |
                                 (unsigned)(~(unsigned)i);
            }
        }
    }
    __syncthreads();

    int cnt = s_cnt < MCAP ? s_cnt : MCAP;
    int P = 128; while (P < cnt) P <<= 1;
    for (int i = threadIdx.x; i < P; i += blockDim.x)
        if (i >= cnt) mkeys[i] = 0ull;
    bitonic_desc(mkeys, P);

    if (threadIdx.x < KRET) {
        int k = threadIdx.x;
        bool valid = (k < cnt);
        float b0 = 0.f, b1 = 0.f, b2 = 0.f, b3 = 0.f;
        float lab = -1.0f, sout = 0.0f;
        if (valid) {
            ull key = mkeys[k];
            float s = __uint_as_float((unsigned)(key >> 32));
            unsigned flat = ~(unsigned)(key & 0xFFFFFFFFull);
            if (s > 0.0f && flat < (unsigned)M) {
                int c = flat / KRET, kk = flat % KRET;
                int base = ((b * NCLS + c) * KRET + kk) * 4;
                b0 = g_cls_boxes[base + 0]; b1 = g_cls_boxes[base + 1];
                b2 = g_cls_boxes[base + 2]; b3 = g_cls_boxes[base + 3];
                lab = (float)c; sout = s;
            }
        }
        int bo = (b * KRET + k) * 4;
        out[bo + 0] = b0; out[bo + 1] = b1; out[bo + 2] = b2; out[bo + 3] = b3;
        out[NB * KRET * 4 + b * KRET + k] = sout;
        out[NB * KRET * 5 + b * KRET + k] = lab;
    }
}

extern "C" void kernel_launch(void* const* d_in, const int* in_sizes, int n_in,
                              void* d_out, int out_size) {
    const float* bboxes  = (const float*)d_in[0];
    const float* scores  = (const float*)d_in[1];
    const float* anchors = (const float*)d_in[2];
    float* out = (float*)d_out;

    decode_kernel<<<(NB * N_ANCH + 255) / 256, 256>>>(bboxes, anchors);
    scan_kernel<<<(TOT4 + 255) / 256, 256>>>(scores);
    topk_nms_kernel<<<dim3(NCLS, NB), 256>>>(scores);
    merge_kernel<<<NB, 512>>>(out);
}

// round 5
// speedup vs baseline: 1.0031x; 1.0013x over previous
#include <cuda_runtime.h>
#include <cuda_bf16.h>
#include <math.h>

#define N_ANCH 49104
#define NCLS   90
#define NB     8
#define KRET   100
#define SCORE_THR 0.3f
#define IOU_THR   0.45f
#define THR_HI 0.98f
#define CAP    2048
#define MCAP   4096
#define TOT    (NB * N_ANCH * NCLS)
#define TOT4   (TOT / 4)

typedef unsigned long long ull;

// ---------------- device scratch ----------------
__device__ float g_boxes[NB * N_ANCH * 4];
__device__ int   g_cnt[NB * NCLS];
__device__ ull   g_cand[(size_t)NB * NCLS * CAP];
__device__ float g_cls_scores[NB * NCLS * KRET];
__device__ float g_cls_boxes[NB * NCLS * KRET * 4];

// ---------------- kernel 1: decode + clip (+ zero counters) ----------------
__global__ void decode_kernel(const float* __restrict__ bboxes,
                              const float* __restrict__ anchors) {
    int idx = blockIdx.x * blockDim.x + threadIdx.x;
    if (idx < NB * NCLS) g_cnt[idx] = 0;
    if (idx >= NB * N_ANCH) return;
    int n = idx % N_ANCH;
    float4 d = ((const float4*)bboxes)[idx];
    float4 a = ((const float4*)anchors)[n];
    float aw = a.z - a.x, ah = a.w - a.y;
    float acx = a.x + 0.5f * aw, acy = a.y + 0.5f * ah;
    float dx = d.x * 0.1f, dy = d.y * 0.1f;
    float dw = fminf(d.z * 0.2f, 4.135f);
    float dh = fminf(d.w * 0.2f, 4.135f);
    float cx = acx + dx * aw, cy = acy + dy * ah;
    float w = aw * expf(dw), h = ah * expf(dh);
    float4 o;
    o.x = fminf(fmaxf(cx - 0.5f * w, 0.0f), 512.0f);
    o.y = fminf(fmaxf(cy - 0.5f * h, 0.0f), 512.0f);
    o.z = fminf(fmaxf(cx + 0.5f * w, 0.0f), 512.0f);
    o.w = fminf(fmaxf(cy + 0.5f * h, 0.0f), 512.0f);
    ((float4*)g_boxes)[idx] = o;
}

// ---------------- kernel 2: single streaming pass, append high candidates ----
__device__ __forceinline__ void try_append(float s, unsigned flat) {
    if (s > THR_HI) {
        unsigned rem = flat % (unsigned)(N_ANCH * NCLS);
        int b = flat / (unsigned)(N_ANCH * NCLS);
        int n = rem / NCLS;
        int c = rem % NCLS;
        int bc = b * NCLS + c;
        int pos = atomicAdd(&g_cnt[bc], 1);
        if (pos < CAP)
            g_cand[(size_t)bc * CAP + pos] =
                ((ull)__float_as_uint(s) << 32) | (unsigned)(~(unsigned)n);
    }
}

__global__ void scan_kernel(const float* __restrict__ scores) {
    unsigned i4 = blockIdx.x * blockDim.x + threadIdx.x;
    if (i4 >= TOT4) return;
    float4 v = ((const float4*)scores)[i4];
    unsigned base = i4 * 4u;
    try_append(v.x, base + 0u);
    try_append(v.y, base + 1u);
    try_append(v.z, base + 2u);
    try_append(v.w, base + 3u);
}

// descending bitonic sort on shared ull keys, P power of two
__device__ void bitonic_desc(ull* k, int P) {
    for (int len = 2; len <= P; len <<= 1) {
        for (int j = len >> 1; j > 0; j >>= 1) {
            __syncthreads();
            for (int i = threadIdx.x; i < P; i += blockDim.x) {
                int ixj = i ^ j;
                if (ixj > i) {
                    bool desc = ((i & len) == 0);
                    ull x = k[i], y = k[ixj];
                    if (desc ? (x < y) : (x > y)) { k[i] = y; k[ixj] = x; }
                }
            }
        }
    }
    __syncthreads();
}

// ---------------- kernel 3: per-(b,c) top-100 + greedy NMS ----------------
__global__ void topk_nms_kernel(const float* __restrict__ scores) {
    int c = blockIdx.x, b = blockIdx.y;
    int bc = b * NCLS + c;

    __shared__ ull keys[CAP];
    __shared__ int s_cnt, s_edge;
    __shared__ unsigned hist[512];
    __shared__ float bx[KRET][4];
    __shared__ float vv[KRET];
    __shared__ unsigned char supp[KRET], keepf[KRET];

    int cnt = g_cnt[bc];
    if (cnt > CAP) cnt = CAP;
    for (int i = threadIdx.x; i < cnt; i += blockDim.x)
        keys[i] = g_cand[(size_t)bc * CAP + i];
    if (threadIdx.x == 0) s_cnt = cnt;
    __syncthreads();

    if (cnt < KRET) {
        // fallback (rare/never): gather more candidates from (0.3, 0.98]
        for (int i = threadIdx.x; i < 512; i += blockDim.x) hist[i] = 0;
        __syncthreads();
        const float invw = 512.0f / (THR_HI - SCORE_THR);
        for (int n = threadIdx.x; n < N_ANCH; n += blockDim.x) {
            float s = scores[((size_t)b * N_ANCH + n) * NCLS + c];
            if (s > SCORE_THR && s <= THR_HI) {
                int bin = (int)((s - SCORE_THR) * invw);
                if (bin > 511) bin = 511;
                atomicAdd(&hist[bin], 1u);
            }
        }
        __syncthreads();
        if (threadIdx.x == 0) {
            int need = KRET - cnt;
            unsigned cum = 0; int edge = 0;
            for (int e = 511; e >= 0; --e) {
                cum += hist[e];
                if ((int)cum >= need) { edge = e; break; }
            }
            s_edge = edge;
        }
        __syncthreads();
        int edge = s_edge;
        for (int n = threadIdx.x; n < N_ANCH; n += blockDim.x) {
            float s = scores[((size_t)b * N_ANCH + n) * NCLS + c];
            if (s > SCORE_THR && s <= THR_HI) {
                int bin = (int)((s - SCORE_THR) * invw);
                if (bin > 511) bin = 511;
                if (bin >= edge) {
                    int pos = atomicAdd(&s_cnt, 1);
                    if (pos < CAP)
                        keys[pos] = ((ull)__float_as_uint(s) << 32) |
                                    (unsigned)(~(unsigned)n);
                }
            }
        }
        __syncthreads();
    }

    int M = s_cnt < CAP ? s_cnt : CAP;
    int P = 128; while (P < M) P <<= 1;
    for (int i = threadIdx.x; i < P; i += blockDim.x)
        if (i >= M) keys[i] = 0ull;
    bitonic_desc(keys, P);

    if (threadIdx.x < KRET) {
        int k = threadIdx.x;
        if (k < M) {
            ull key = keys[k];
            float s = __uint_as_float((unsigned)(key >> 32));
            unsigned idx = ~(unsigned)(key & 0xFFFFFFFFull);
            vv[k] = s;
            const float4 bp = ((const float4*)g_boxes)[(size_t)b * N_ANCH + idx];
            bx[k][0] = bp.x; bx[k][1] = bp.y; bx[k][2] = bp.z; bx[k][3] = bp.w;
        } else {
            vv[k] = -1.0f;
            bx[k][0] = bx[k][1] = bx[k][2] = bx[k][3] = 0.0f;
        }
        supp[k] = 0; keepf[k] = 0;
    }
    __syncthreads();

    // greedy NMS, matches jax scan order
    for (int i = 0; i < KRET; ++i) {
        bool keep_i = (!supp[i]) && (vv[i] > 0.0f);
        if (threadIdx.x == 0) keepf[i] = keep_i ? 1 : 0;
        int j = threadIdx.x;
        if (keep_i && j < KRET && j != i) {
            float xx1 = fmaxf(bx[i][0], bx[j][0]);
            float yy1 = fmaxf(bx[i][1], bx[j][1]);
            float xx2 = fminf(bx[i][2], bx[j][2]);
            float yy2 = fminf(bx[i][3], bx[j][3]);
            float w = fmaxf(xx2 - xx1, 0.0f);
            float h = fmaxf(yy2 - yy1, 0.0f);
            float inter = w * h;
            float ai = (bx[i][2] - bx[i][0]) * (bx[i][3] - bx[i][1]);
            float aj = (bx[j][2] - bx[j][0]) * (bx[j][3] - bx[j][1]);
            float iou = inter / (ai + aj - inter + 1e-8f);
            if (iou > IOU_THR) supp[j] = 1;
        }
        __syncthreads();
    }

    if (threadIdx.x < KRET) {
        int k = threadIdx.x;
        int base = bc * KRET + k;
        g_cls_scores[base] = keepf[k] ? vv[k] : -1.0f;
        g_cls_boxes[base * 4 + 0] = bx[k][0];
        g_cls_boxes[base * 4 + 1] = bx[k][1];
        g_cls_boxes[base * 4 + 2] = bx[k][2];
        g_cls_boxes[base * 4 + 3] = bx[k][3];
    }
}

// ---------------- kernel 4: merge via histogram selection ----------------
__global__ void merge_kernel(float* __restrict__ out) {
    __shared__ unsigned hist[513];   // bin 0 = catch-all (0, 0.98]
    __shared__ ull mkeys[MCAP];
    __shared__ int s_cnt, s_edge;
    const int M = NCLS * KRET;       // 9000
    int b = blockIdx.x;

    for (int i = threadIdx.x; i < 513; i += blockDim.x) hist[i] = 0;
    if (threadIdx.x == 0) s_cnt = 0;
    __syncthreads();

    const float invw = 512.0f / (1.0f - THR_HI);
    for (int i = threadIdx.x; i < M; i += blockDim.x) {
        float s = g_cls_scores[b * M + i];
        if (s > 0.0f) {
            int bin = (s > THR_HI) ? 1 + min(511, (int)((s - THR_HI) * invw)) : 0;
            atomicAdd(&hist[bin], 1u);
        }
    }
    __syncthreads();

    if (threadIdx.x == 0) {
        unsigned cum = 0; int edge = 0;
        for (int e = 512; e >= 0; --e) {
            cum += hist[e];
            if (cum >= KRET) { edge = e; break; }
        }
        s_edge = edge;
    }
    __syncthreads();
    int edge = s_edge;

    for (int i = threadIdx.x; i < M; i += blockDim.x) {
        float s = g_cls_scores[b * M + i];
        if (s > 0.0f) {
            int bin = (s > THR_HI) ? 1 + min(511, (int)((s - THR_HI) * invw)) : 0;
            if (bin >= edge) {
                int pos = atomicAdd(&s_cnt, 1);
                if (pos < MCAP)
                    mkeys[pos] = ((ull)__float_as_uint(s) << 32) |
                                 (unsigned)(~(unsigned)i);
            }
        }
    }
    __syncthreads();

    int cnt = s_cnt < MCAP ? s_cnt : MCAP;
    int P = 128; while (P < cnt) P <<= 1;
    for (int i = threadIdx.x; i < P; i += blockDim.x)
        if (i >= cnt) mkeys[i] = 0ull;
    bitonic_desc(mkeys, P);

    if (threadIdx.x < KRET) {
        int k = threadIdx.x;
        bool valid = (k < cnt);
        float b0 = 0.f, b1 = 0.f, b2 = 0.f, b3 = 0.f;
        float lab = -1.0f, sout = 0.0f;
        if (valid) {
            ull key = mkeys[k];
            float s = __uint_as_float((unsigned)(key >> 32));
            unsigned flat = ~(unsigned)(key & 0xFFFFFFFFull);
            if (s > 0.0f && flat < (unsigned)M) {
                int c = flat / KRET, kk = flat % KRET;
                int base = ((b * NCLS + c) * KRET + kk) * 4;
                b0 = g_cls_boxes[base + 0]; b1 = g_cls_boxes[base + 1];
                b2 = g_cls_boxes[base + 2]; b3 = g_cls_boxes[base + 3];
                lab = (float)c; sout = s;
            }
        }
        int bo = (b * KRET + k) * 4;
        out[bo + 0] = b0; out[bo + 1] = b1; out[bo + 2] = b2; out[bo + 3] = b3;
        out[NB * KRET * 4 + b * KRET + k] = sout;
        out[NB * KRET * 5 + b * KRET + k] = lab;
    }
}

extern "C" void kernel_launch(void* const* d_in, const int* in_sizes, int n_in,
                              void* d_out, int out_size) {
    const float* bboxes  = (const float*)d_in[0];
    const float* scores  = (const float*)d_in[1];
    const float* anchors = (const float*)d_in[2];
    float* out = (float*)d_out;

    decode_kernel<<<(NB * N_ANCH + 255) / 256, 256>>>(bboxes, anchors);
    scan_kernel<<<(TOT4 + 255) / 256, 256>>>(scores);
    topk_nms_kernel<<<dim3(NCLS, NB), 256>>>(scores);
    merge_kernel<<<NB, 512>>>(out);
}

// round 6
// speedup vs baseline: 3.8043x; 3.7925x over previous
#include <cuda_runtime.h>
#include <cuda_bf16.h>
#include <math.h>

#define N_ANCH 49104
#define NCLS   90
#define NB     8
#define KRET   100
#define SCORE_THR 0.3f
#define IOU_THR   0.45f
#define THR_HI 0.9955f
#define CAP    2048
#define MCAP   4096
#define CNT_STRIDE 32
#define TOT    (NB * N_ANCH * NCLS)
#define TOT4   (TOT / 4)

typedef unsigned long long ull;

// ---------------- device scratch ----------------
__device__ float g_boxes[NB * N_ANCH * 4];
__device__ int   g_cnt[NB * NCLS * CNT_STRIDE];          // 128B-padded counters
__device__ ull   g_cand[(size_t)NB * NCLS * CAP];
__device__ float g_cls_scores[NB * NCLS * KRET];
__device__ float g_cls_boxes[NB * NCLS * KRET * 4];

// ---------------- kernel 1: decode + clip (+ zero counters) ----------------
__global__ void decode_kernel(const float* __restrict__ bboxes,
                              const float* __restrict__ anchors) {
    int idx = blockIdx.x * blockDim.x + threadIdx.x;
    if (idx < NB * NCLS * CNT_STRIDE) g_cnt[idx] = 0;
    if (idx >= NB * N_ANCH) return;
    int n = idx % N_ANCH;
    float4 d = ((const float4*)bboxes)[idx];
    float4 a = ((const float4*)anchors)[n];
    float aw = a.z - a.x, ah = a.w - a.y;
    float acx = a.x + 0.5f * aw, acy = a.y + 0.5f * ah;
    float dx = d.x * 0.1f, dy = d.y * 0.1f;
    float dw = fminf(d.z * 0.2f, 4.135f);
    float dh = fminf(d.w * 0.2f, 4.135f);
    float cx = acx + dx * aw, cy = acy + dy * ah;
    float w = aw * expf(dw), h = ah * expf(dh);
    float4 o;
    o.x = fminf(fmaxf(cx - 0.5f * w, 0.0f), 512.0f);
    o.y = fminf(fmaxf(cy - 0.5f * h, 0.0f), 512.0f);
    o.z = fminf(fmaxf(cx + 0.5f * w, 0.0f), 512.0f);
    o.w = fminf(fmaxf(cy + 0.5f * h, 0.0f), 512.0f);
    ((float4*)g_boxes)[idx] = o;
}

// ---------------- kernel 2: single streaming pass, append high candidates ----
__device__ __forceinline__ void try_append(float s, unsigned flat) {
    if (s > THR_HI) {
        unsigned rem = flat % (unsigned)(N_ANCH * NCLS);
        int b = flat / (unsigned)(N_ANCH * NCLS);
        int n = rem / NCLS;
        int c = rem % NCLS;
        int bc = b * NCLS + c;
        int pos = atomicAdd(&g_cnt[bc * CNT_STRIDE], 1);
        if (pos < CAP)
            g_cand[(size_t)bc * CAP + pos] =
                ((ull)__float_as_uint(s) << 32) | (unsigned)(~(unsigned)n);
    }
}

__global__ void scan_kernel(const float* __restrict__ scores) {
    unsigned i4 = blockIdx.x * blockDim.x + threadIdx.x;
    if (i4 >= TOT4) return;
    float4 v = ((const float4*)scores)[i4];
    float mx = fmaxf(fmaxf(v.x, v.y), fmaxf(v.z, v.w));
    if (mx <= THR_HI) return;
    unsigned base = i4 * 4u;
    try_append(v.x, base + 0u);
    try_append(v.y, base + 1u);
    try_append(v.z, base + 2u);
    try_append(v.w, base + 3u);
}

// descending bitonic sort on shared ull keys, P power of two
__device__ void bitonic_desc(ull* k, int P) {
    for (int len = 2; len <= P; len <<= 1) {
        for (int j = len >> 1; j > 0; j >>= 1) {
            __syncthreads();
            for (int i = threadIdx.x; i < P; i += blockDim.x) {
                int ixj = i ^ j;
                if (ixj > i) {
                    bool desc = ((i & len) == 0);
                    ull x = k[i], y = k[ixj];
                    if (desc ? (x < y) : (x > y)) { k[i] = y; k[ixj] = x; }
                }
            }
        }
    }
    __syncthreads();
}

// ---------------- kernel 3: per-(b,c) top-100 + bitmask greedy NMS ----------
__global__ void topk_nms_kernel(const float* __restrict__ scores) {
    int c = blockIdx.x, b = blockIdx.y;
    int bc = b * NCLS + c;

    __shared__ ull keys[CAP];
    __shared__ int s_cnt, s_edge;
    __shared__ unsigned hist[512];
    __shared__ float bx[128][4];      // padded past KRET for safe warp lanes
    __shared__ float vv[KRET];
    __shared__ unsigned row[KRET][4]; // iou bit-matrix rows
    __shared__ unsigned char keepf[KRET];

    int cnt = g_cnt[bc * CNT_STRIDE];
    if (cnt > CAP) cnt = CAP;
    for (int i = threadIdx.x; i < cnt; i += blockDim.x)
        keys[i] = g_cand[(size_t)bc * CAP + i];
    if (threadIdx.x == 0) s_cnt = cnt;
    __syncthreads();

    if (cnt < KRET) {
        // fallback (statistically never on this input, kept for correctness):
        // histogram-select more candidates from (SCORE_THR, THR_HI]
        for (int i = threadIdx.x; i < 512; i += blockDim.x) hist[i] = 0;
        __syncthreads();
        const float invw = 512.0f / (THR_HI - SCORE_THR);
        for (int n = threadIdx.x; n < N_ANCH; n += blockDim.x) {
            float s = scores[((size_t)b * N_ANCH + n) * NCLS + c];
            if (s > SCORE_THR && s <= THR_HI) {
                int bin = (int)((s - SCORE_THR) * invw);
                if (bin > 511) bin = 511;
                atomicAdd(&hist[bin], 1u);
            }
        }
        __syncthreads();
        if (threadIdx.x == 0) {
            int need = KRET - cnt;
            unsigned cum = 0; int edge = 0;
            for (int e = 511; e >= 0; --e) {
                cum += hist[e];
                if ((int)cum >= need) { edge = e; break; }
            }
            s_edge = edge;
        }
        __syncthreads();
        int edge = s_edge;
        for (int n = threadIdx.x; n < N_ANCH; n += blockDim.x) {
            float s = scores[((size_t)b * N_ANCH + n) * NCLS + c];
            if (s > SCORE_THR && s <= THR_HI) {
                int bin = (int)((s - SCORE_THR) * invw);
                if (bin > 511) bin = 511;
                if (bin >= edge) {
                    int pos = atomicAdd(&s_cnt, 1);
                    if (pos < CAP)
                        keys[pos] = ((ull)__float_as_uint(s) << 32) |
                                    (unsigned)(~(unsigned)n);
                }
            }
        }
        __syncthreads();
    }

    int M = s_cnt < CAP ? s_cnt : CAP;
    int P = 128; while (P < M) P <<= 1;
    for (int i = threadIdx.x; i < P; i += blockDim.x)
        if (i >= M) keys[i] = 0ull;
    bitonic_desc(keys, P);

    // gather top-100 boxes
    if (threadIdx.x < 128) {
        int k = threadIdx.x;
        if (k < KRET && k < M) {
            ull key = keys[k];
            float s = __uint_as_float((unsigned)(key >> 32));
            unsigned idx = ~(unsigned)(key & 0xFFFFFFFFull);
            vv[k] = s;
            const float4 bp = ((const float4*)g_boxes)[(size_t)b * N_ANCH + idx];
            bx[k][0] = bp.x; bx[k][1] = bp.y; bx[k][2] = bp.z; bx[k][3] = bp.w;
        } else {
            if (k < KRET) vv[k] = -1.0f;
            bx[k][0] = bx[k][1] = bx[k][2] = bx[k][3] = 0.0f;
        }
    }
    __syncthreads();

    // build IoU bit-matrix: warp w covers columns j = 32w..32w+31 (4 warps)
    int wid = threadIdx.x >> 5, lane = threadIdx.x & 31;
    if (wid < 4) {
        int j = threadIdx.x;  // 0..127
        float jx1 = bx[j][0], jy1 = bx[j][1], jx2 = bx[j][2], jy2 = bx[j][3];
        float aj = (jx2 - jx1) * (jy2 - jy1);
        for (int i = 0; i < KRET; ++i) {
            float xx1 = fmaxf(bx[i][0], jx1);
            float yy1 = fmaxf(bx[i][1], jy1);
            float xx2 = fminf(bx[i][2], jx2);
            float yy2 = fminf(bx[i][3], jy2);
            float w = fmaxf(xx2 - xx1, 0.0f);
            float h = fmaxf(yy2 - yy1, 0.0f);
            float inter = w * h;
            float ai = (bx[i][2] - bx[i][0]) * (bx[i][3] - bx[i][1]);
            float iou = inter / (ai + aj - inter + 1e-8f);
            bool pred = (j < KRET) && (j != i) && (iou > IOU_THR);
            unsigned bits = __ballot_sync(0xFFFFFFFFu, pred);
            if (lane == 0) row[i][wid] = bits;
        }
    }
    __syncthreads();

    // serial greedy scan on bitmasks (thread 0)
    if (threadIdx.x == 0) {
        unsigned sup0 = 0, sup1 = 0, sup2 = 0, sup3 = 0;
        for (int i = 0; i < KRET; ++i) {
            unsigned sw = (i < 32) ? sup0 : (i < 64) ? sup1 : (i < 96) ? sup2 : sup3;
            bool keep = !((sw >> (i & 31)) & 1u) && (vv[i] > 0.0f);
            keepf[i] = keep ? 1 : 0;
            if (keep) {
                sup0 |= row[i][0]; sup1 |= row[i][1];
                sup2 |= row[i][2]; sup3 |= row[i][3];
            }
        }
    }
    __syncthreads();

    if (threadIdx.x < KRET) {
        int k = threadIdx.x;
        int base = bc * KRET + k;
        g_cls_scores[base] = keepf[k] ? vv[k] : -1.0f;
        g_cls_boxes[base * 4 + 0] = bx[k][0];
        g_cls_boxes[base * 4 + 1] = bx[k][1];
        g_cls_boxes[base * 4 + 2] = bx[k][2];
        g_cls_boxes[base * 4 + 3] = bx[k][3];
    }
}

// ---------------- kernel 4: merge via histogram selection ----------------
__global__ void merge_kernel(float* __restrict__ out) {
    __shared__ unsigned hist[513];   // bin 0 = catch-all (0, THR_HI]
    __shared__ ull mkeys[MCAP];
    __shared__ int s_cnt, s_edge;
    const int M = NCLS * KRET;       // 9000
    int b = blockIdx.x;

    for (int i = threadIdx.x; i < 513; i += blockDim.x) hist[i] = 0;
    if (threadIdx.x == 0) s_cnt = 0;
    __syncthreads();

    const float invw = 512.0f / (1.0f - THR_HI);
    for (int i = threadIdx.x; i < M; i += blockDim.x) {
        float s = g_cls_scores[b * M + i];
        if (s > 0.0f) {
            int bin = (s > THR_HI) ? 1 + min(511, (int)((s - THR_HI) * invw)) : 0;
            atomicAdd(&hist[bin], 1u);
        }
    }
    __syncthreads();

    if (threadIdx.x == 0) {
        unsigned cum = 0; int edge = 0;
        for (int e = 512; e >= 0; --e) {
            cum += hist[e];
            if (cum >= KRET) { edge = e; break; }
        }
        s_edge = edge;
    }
    __syncthreads();
    int edge = s_edge;

    for (int i = threadIdx.x; i < M; i += blockDim.x) {
        float s = g_cls_scores[b * M + i];
        if (s > 0.0f) {
            int bin = (s > THR_HI) ? 1 + min(511, (int)((s - THR_HI) * invw)) : 0;
            if (bin >= edge) {
                int pos = atomicAdd(&s_cnt, 1);
                if (pos < MCAP)
                    mkeys[pos] = ((ull)__float_as_uint(s) << 32) |
                                 (unsigned)(~(unsigned)i);
            }
        }
    }
    __syncthreads();

    int cnt = s_cnt < MCAP ? s_cnt : MCAP;
    int P = 128; while (P < cnt) P <<= 1;
    for (int i = threadIdx.x; i < P; i += blockDim.x)
        if (i >= cnt) mkeys[i] = 0ull;
    bitonic_desc(mkeys, P);

    if (threadIdx.x < KRET) {
        int k = threadIdx.x;
        bool valid = (k < cnt);
        float b0 = 0.f, b1 = 0.f, b2 = 0.f, b3 = 0.f;
        float lab = -1.0f, sout = 0.0f;
        if (valid) {
            ull key = mkeys[k];
            float s = __uint_as_float((unsigned)(key >> 32));
            unsigned flat = ~(unsigned)(key & 0xFFFFFFFFull);
            if (s > 0.0f && flat < (unsigned)M) {
                int c = flat / KRET, kk = flat % KRET;
                int base = ((b * NCLS + c) * KRET + kk) * 4;
                b0 = g_cls_boxes[base + 0]; b1 = g_cls_boxes[base + 1];
                b2 = g_cls_boxes[base + 2]; b3 = g_cls_boxes[base + 3];
                lab = (float)c; sout = s;
            }
        }
        int bo = (b * KRET + k) * 4;
        out[bo + 0] = b0; out[bo + 1] = b1; out[bo + 2] = b2; out[bo + 3] = b3;
        out[NB * KRET * 4 + b * KRET + k] = sout;
        out[NB * KRET * 5 + b * KRET + k] = lab;
    }
}

extern "C" void kernel_launch(void* const* d_in, const int* in_sizes, int n_in,
                              void* d_out, int out_size) {
    const float* bboxes  = (const float*)d_in[0];
    const float* scores  = (const float*)d_in[1];
    const float* anchors = (const float*)d_in[2];
    float* out = (float*)d_out;

    decode_kernel<<<(NB * N_ANCH + 255) / 256, 256>>>(bboxes, anchors);
    scan_kernel<<<(TOT4 + 255) / 256, 256>>>(scores);
    topk_nms_kernel<<<dim3(NCLS, NB), 256>>>(scores);
    merge_kernel<<<NB, 512>>>(out);
}

// round 7
// speedup vs baseline: 3.8055x; 1.0003x over previous
#include <cuda_runtime.h>
#include <cuda_bf16.h>
#include <math.h>

#define N_ANCH 49104
#define NCLS   90
#define NB     8
#define KRET   100
#define SCORE_THR 0.3f
#define IOU_THR   0.45f
#define THR_HI 0.9955f
#define CAP    2048
#define MCAP   4096
#define CNT_STRIDE 32
#define TOT    (NB * N_ANCH * NCLS)
#define TOT4   (TOT / 4)

typedef unsigned long long ull;

// ---------------- device scratch ----------------
__device__ float g_boxes[NB * N_ANCH * 4];
__device__ int   g_cnt[NB * NCLS * CNT_STRIDE];          // 128B-padded counters
__device__ ull   g_cand[(size_t)NB * NCLS * CAP];
__device__ float g_cls_scores[NB * NCLS * KRET];
__device__ float g_cls_boxes[NB * NCLS * KRET * 4];

// ---------------- kernel 1: decode + clip (+ zero counters) ----------------
__global__ void decode_kernel(const float* __restrict__ bboxes,
                              const float* __restrict__ anchors) {
    int idx = blockIdx.x * blockDim.x + threadIdx.x;
    if (idx < NB * NCLS * CNT_STRIDE) g_cnt[idx] = 0;
    if (idx >= NB * N_ANCH) return;
    int n = idx % N_ANCH;
    float4 d = ((const float4*)bboxes)[idx];
    float4 a = ((const float4*)anchors)[n];
    float aw = a.z - a.x, ah = a.w - a.y;
    float acx = a.x + 0.5f * aw, acy = a.y + 0.5f * ah;
    float dx = d.x * 0.1f, dy = d.y * 0.1f;
    float dw = fminf(d.z * 0.2f, 4.135f);
    float dh = fminf(d.w * 0.2f, 4.135f);
    float cx = acx + dx * aw, cy = acy + dy * ah;
    float w = aw * expf(dw), h = ah * expf(dh);
    float4 o;
    o.x = fminf(fmaxf(cx - 0.5f * w, 0.0f), 512.0f);
    o.y = fminf(fmaxf(cy - 0.5f * h, 0.0f), 512.0f);
    o.z = fminf(fmaxf(cx + 0.5f * w, 0.0f), 512.0f);
    o.w = fminf(fmaxf(cy + 0.5f * h, 0.0f), 512.0f);
    ((float4*)g_boxes)[idx] = o;
}

// ---------------- kernel 2: single streaming pass, append high candidates ----
__device__ __forceinline__ void try_append(float s, unsigned flat) {
    if (s > THR_HI) {
        unsigned rem = flat % (unsigned)(N_ANCH * NCLS);
        int b = flat / (unsigned)(N_ANCH * NCLS);
        int n = rem / NCLS;
        int c = rem % NCLS;
        int bc = b * NCLS + c;
        int pos = atomicAdd(&g_cnt[bc * CNT_STRIDE], 1);
        if (pos < CAP)
            g_cand[(size_t)bc * CAP + pos] =
                ((ull)__float_as_uint(s) << 32) | (unsigned)(~(unsigned)n);
    }
}

__global__ void scan_kernel(const float* __restrict__ scores) {
    unsigned i4 = blockIdx.x * blockDim.x + threadIdx.x;
    if (i4 >= TOT4) return;
    float4 v = ((const float4*)scores)[i4];
    float mx = fmaxf(fmaxf(v.x, v.y), fmaxf(v.z, v.w));
    if (mx <= THR_HI) return;
    unsigned base = i4 * 4u;
    try_append(v.x, base + 0u);
    try_append(v.y, base + 1u);
    try_append(v.z, base + 2u);
    try_append(v.w, base + 3u);
}

// descending bitonic sort on shared ull keys, P power of two
__device__ void bitonic_desc(ull* k, int P) {
    for (int len = 2; len <= P; len <<= 1) {
        for (int j = len >> 1; j > 0; j >>= 1) {
            __syncthreads();
            for (int i = threadIdx.x; i < P; i += blockDim.x) {
                int ixj = i ^ j;
                if (ixj > i) {
                    bool desc = ((i & len) == 0);
                    ull x = k[i], y = k[ixj];
                    if (desc ? (x < y) : (x > y)) { k[i] = y; k[ixj] = x; }
                }
            }
        }
    }
    __syncthreads();
}

// ---------------- kernel 3: per-(b,c) top-100 + bitmask greedy NMS ----------
__global__ void topk_nms_kernel(const float* __restrict__ scores) {
    int c = blockIdx.x, b = blockIdx.y;
    int bc = b * NCLS + c;

    __shared__ ull keys[CAP];
    __shared__ int s_cnt, s_edge;
    __shared__ unsigned hist[512];
    __shared__ float bx[128][4];      // padded past KRET for safe warp lanes
    __shared__ float vv[KRET];
    __shared__ unsigned row[KRET][4]; // iou bit-matrix rows
    __shared__ unsigned char keepf[KRET];

    int cnt = g_cnt[bc * CNT_STRIDE];
    if (cnt > CAP) cnt = CAP;
    for (int i = threadIdx.x; i < cnt; i += blockDim.x)
        keys[i] = g_cand[(size_t)bc * CAP + i];
    if (threadIdx.x == 0) s_cnt = cnt;
    __syncthreads();

    if (cnt < KRET) {
        // fallback (statistically never on this input, kept for correctness):
        // histogram-select more candidates from (SCORE_THR, THR_HI]
        for (int i = threadIdx.x; i < 512; i += blockDim.x) hist[i] = 0;
        __syncthreads();
        const float invw = 512.0f / (THR_HI - SCORE_THR);
        for (int n = threadIdx.x; n < N_ANCH; n += blockDim.x) {
            float s = scores[((size_t)b * N_ANCH + n) * NCLS + c];
            if (s > SCORE_THR && s <= THR_HI) {
                int bin = (int)((s - SCORE_THR) * invw);
                if (bin > 511) bin = 511;
                atomicAdd(&hist[bin], 1u);
            }
        }
        __syncthreads();
        if (threadIdx.x == 0) {
            int need = KRET - cnt;
            unsigned cum = 0; int edge = 0;
            for (int e = 511; e >= 0; --e) {
                cum += hist[e];
                if ((int)cum >= need) { edge = e; break; }
            }
            s_edge = edge;
        }
        __syncthreads();
        int edge = s_edge;
        for (int n = threadIdx.x; n < N_ANCH; n += blockDim.x) {
            float s = scores[((size_t)b * N_ANCH + n) * NCLS + c];
            if (s > SCORE_THR && s <= THR_HI) {
                int bin = (int)((s - SCORE_THR) * invw);
                if (bin > 511) bin = 511;
                if (bin >= edge) {
                    int pos = atomicAdd(&s_cnt, 1);
                    if (pos < CAP)
                        keys[pos] = ((ull)__float_as_uint(s) << 32) |
                                    (unsigned)(~(unsigned)n);
                }
            }
        }
        __syncthreads();
    }

    int M = s_cnt < CAP ? s_cnt : CAP;
    int P = 128; while (P < M) P <<= 1;
    for (int i = threadIdx.x; i < P; i += blockDim.x)
        if (i >= M) keys[i] = 0ull;
    bitonic_desc(keys, P);

    // gather top-100 boxes
    if (threadIdx.x < 128) {
        int k = threadIdx.x;
        if (k < KRET && k < M) {
            ull key = keys[k];
            float s = __uint_as_float((unsigned)(key >> 32));
            unsigned idx = ~(unsigned)(key & 0xFFFFFFFFull);
            vv[k] = s;
            const float4 bp = ((const float4*)g_boxes)[(size_t)b * N_ANCH + idx];
            bx[k][0] = bp.x; bx[k][1] = bp.y; bx[k][2] = bp.z; bx[k][3] = bp.w;
        } else {
            if (k < KRET) vv[k] = -1.0f;
            bx[k][0] = bx[k][1] = bx[k][2] = bx[k][3] = 0.0f;
        }
    }
    __syncthreads();

    // build IoU bit-matrix: warp w covers columns j = 32w..32w+31 (4 warps)
    int wid = threadIdx.x >> 5, lane = threadIdx.x & 31;
    if (wid < 4) {
        int j = threadIdx.x;  // 0..127
        float jx1 = bx[j][0], jy1 = bx[j][1], jx2 = bx[j][2], jy2 = bx[j][3];
        float aj = (jx2 - jx1) * (jy2 - jy1);
        for (int i = 0; i < KRET; ++i) {
            float xx1 = fmaxf(bx[i][0], jx1);
            float yy1 = fmaxf(bx[i][1], jy1);
            float xx2 = fminf(bx[i][2], jx2);
            float yy2 = fminf(bx[i][3], jy2);
            float w = fmaxf(xx2 - xx1, 0.0f);
            float h = fmaxf(yy2 - yy1, 0.0f);
            float inter = w * h;
            float ai = (bx[i][2] - bx[i][0]) * (bx[i][3] - bx[i][1]);
            float iou = inter / (ai + aj - inter + 1e-8f);
            bool pred = (j < KRET) && (j != i) && (iou > IOU_THR);
            unsigned bits = __ballot_sync(0xFFFFFFFFu, pred);
            if (lane == 0) row[i][wid] = bits;
        }
    }
    __syncthreads();

    // serial greedy scan on bitmasks (thread 0)
    if (threadIdx.x == 0) {
        unsigned sup0 = 0, sup1 = 0, sup2 = 0, sup3 = 0;
        for (int i = 0; i < KRET; ++i) {
            unsigned sw = (i < 32) ? sup0 : (i < 64) ? sup1 : (i < 96) ? sup2 : sup3;
            bool keep = !((sw >> (i & 31)) & 1u) && (vv[i] > 0.0f);
            keepf[i] = keep ? 1 : 0;
            if (keep) {
                sup0 |= row[i][0]; sup1 |= row[i][1];
                sup2 |= row[i][2]; sup3 |= row[i][3];
            }
        }
    }
    __syncthreads();

    if (threadIdx.x < KRET) {
        int k = threadIdx.x;
        int base = bc * KRET + k;
        g_cls_scores[base] = keepf[k] ? vv[k] : -1.0f;
        g_cls_boxes[base * 4 + 0] = bx[k][0];
        g_cls_boxes[base * 4 + 1] = bx[k][1];
        g_cls_boxes[base * 4 + 2] = bx[k][2];
        g_cls_boxes[base * 4 + 3] = bx[k][3];
    }
}

// ---------------- kernel 4: merge via histogram selection ----------------
__global__ void merge_kernel(float* __restrict__ out) {
    __shared__ unsigned hist[513];   // bin 0 = catch-all (0, THR_HI]
    __shared__ ull mkeys[MCAP];
    __shared__ int s_cnt, s_edge;
    const int M = NCLS * KRET;       // 9000
    int b = blockIdx.x;

    for (int i = threadIdx.x; i < 513; i += blockDim.x) hist[i] = 0;
    if (threadIdx.x == 0) s_cnt = 0;
    __syncthreads();

    const float invw = 512.0f / (1.0f - THR_HI);
    for (int i = threadIdx.x; i < M; i += blockDim.x) {
        float s = g_cls_scores[b * M + i];
        if (s > 0.0f) {
            int bin = (s > THR_HI) ? 1 + min(511, (int)((s - THR_HI) * invw)) : 0;
            atomicAdd(&hist[bin], 1u);
        }
    }
    __syncthreads();

    if (threadIdx.x == 0) {
        unsigned cum = 0; int edge = 0;
        for (int e = 512; e >= 0; --e) {
            cum += hist[e];
            if (cum >= KRET) { edge = e; break; }
        }
        s_edge = edge;
    }
    __syncthreads();
    int edge = s_edge;

    for (int i = threadIdx.x; i < M; i += blockDim.x) {
        float s = g_cls_scores[b * M + i];
        if (s > 0.0f) {
            int bin = (s > THR_HI) ? 1 + min(511, (int)((s - THR_HI) * invw)) : 0;
            if (bin >= edge) {
                int pos = atomicAdd(&s_cnt, 1);
                if (pos < MCAP)
                    mkeys[pos] = ((ull)__float_as_uint(s) << 32) |
                                 (unsigned)(~(unsigned)i);
            }
        }
    }
    __syncthreads();

    int cnt = s_cnt < MCAP ? s_cnt : MCAP;
    int P = 128; while (P < cnt) P <<= 1;
    for (int i = threadIdx.x; i < P; i += blockDim.x)
        if (i >= cnt) mkeys[i] = 0ull;
    bitonic_desc(mkeys, P);

    if (threadIdx.x < KRET) {
        int k = threadIdx.x;
        bool valid = (k < cnt);
        float b0 = 0.f, b1 = 0.f, b2 = 0.f, b3 = 0.f;
        float lab = -1.0f, sout = 0.0f;
        if (valid) {
            ull key = mkeys[k];
            float s = __uint_as_float((unsigned)(key >> 32));
            unsigned flat = ~(unsigned)(key & 0xFFFFFFFFull);
            if (s > 0.0f && flat < (unsigned)M) {
                int c = flat / KRET, kk = flat % KRET;
                int base = ((b * NCLS + c) * KRET + kk) * 4;
                b0 = g_cls_boxes[base + 0]; b1 = g_cls_boxes[base + 1];
                b2 = g_cls_boxes[base + 2]; b3 = g_cls_boxes[base + 3];
                lab = (float)c; sout = s;
            }
        }
        int bo = (b * KRET + k) * 4;
        out[bo + 0] = b0; out[bo + 1] = b1; out[bo + 2] = b2; out[bo + 3] = b3;
        out[NB * KRET * 4 + b * KRET + k] = sout;
        out[NB * KRET * 5 + b * KRET + k] = lab;
    }
}

extern "C" void kernel_launch(void* const* d_in, const int* in_sizes, int n_in,
                              void* d_out, int out_size) {
    const float* bboxes  = (const float*)d_in[0];
    const float* scores  = (const float*)d_in[1];
    const float* anchors = (const float*)d_in[2];
    float* out = (float*)d_out;

    decode_kernel<<<(NB * N_ANCH + 255) / 256, 256>>>(bboxes, anchors);
    scan_kernel<<<(TOT4 + 255) / 256, 256>>>(scores);
    topk_nms_kernel<<<dim3(NCLS, NB), 256>>>(scores);
    merge_kernel<<<NB, 512>>>(out);
}

// round 8
// speedup vs baseline: 4.4428x; 1.1675x over previous
#include <cuda_runtime.h>
#include <cuda_bf16.h>
#include <math.h>

#define N_ANCH 49104
#define NCLS   90
#define NB     8
#define KRET   100
#define SCORE_THR 0.3f
#define IOU_THR   0.45f
#define THR_HI 0.9955f
#define CAP    2048
#define MCAP   4096
#define CNT_STRIDE 32
#define TOT    (NB * N_ANCH * NCLS)
#define TOT4   (TOT / 4)

typedef unsigned long long ull;

// ---------------- device scratch ----------------
__device__ int   g_cnt[NB * NCLS * CNT_STRIDE];   // 128B-padded counters (zeroed by topk after use)
__device__ ull   g_cand[(size_t)NB * NCLS * CAP];
__device__ float g_cls_scores[NB * NCLS * KRET];
__device__ float g_cls_boxes[NB * NCLS * KRET * 4];

// ---------------- kernel 1: single streaming pass, append high candidates ----
__device__ __forceinline__ void try_append(float s, unsigned flat) {
    if (s > THR_HI) {
        unsigned rem = flat % (unsigned)(N_ANCH * NCLS);
        int b = flat / (unsigned)(N_ANCH * NCLS);
        int n = rem / NCLS;
        int c = rem % NCLS;
        int bc = b * NCLS + c;
        int pos = atomicAdd(&g_cnt[bc * CNT_STRIDE], 1);
        if (pos < CAP)
            g_cand[(size_t)bc * CAP + pos] =
                ((ull)__float_as_uint(s) << 32) | (unsigned)(~(unsigned)n);
    }
}

__device__ __forceinline__ void scan_vec(float4 v, unsigned i4) {
    float mx = fmaxf(fmaxf(v.x, v.y), fmaxf(v.z, v.w));
    if (mx <= THR_HI) return;
    unsigned base = i4 * 4u;
    try_append(v.x, base + 0u);
    try_append(v.y, base + 1u);
    try_append(v.z, base + 2u);
    try_append(v.w, base + 3u);
}

__global__ void scan_kernel(const float* __restrict__ scores) {
    unsigned t = blockIdx.x * blockDim.x + threadIdx.x;
    unsigned S = gridDim.x * blockDim.x;
    unsigned i0 = t, i1 = t + S, i2 = t + 2u * S, i3 = t + 3u * S;
    const float4* sp = (const float4*)scores;
    // front-batched independent loads (MLP=4)
    float4 v0, v1, v2, v3;
    bool b0 = i0 < TOT4, b1 = i1 < TOT4, b2 = i2 < TOT4, b3 = i3 < TOT4;
    if (b0) v0 = sp[i0];
    if (b1) v1 = sp[i1];
    if (b2) v2 = sp[i2];
    if (b3) v3 = sp[i3];
    if (b0) scan_vec(v0, i0);
    if (b1) scan_vec(v1, i1);
    if (b2) scan_vec(v2, i2);
    if (b3) scan_vec(v3, i3);
}

// descending bitonic sort on shared ull keys, P power of two
__device__ void bitonic_desc(ull* k, int P) {
    for (int len = 2; len <= P; len <<= 1) {
        for (int j = len >> 1; j > 0; j >>= 1) {
            __syncthreads();
            for (int i = threadIdx.x; i < P; i += blockDim.x) {
                int ixj = i ^ j;
                if (ixj > i) {
                    bool desc = ((i & len) == 0);
                    ull x = k[i], y = k[ixj];
                    if (desc ? (x < y) : (x > y)) { k[i] = y; k[ixj] = x; }
                }
            }
        }
    }
    __syncthreads();
}

// ---------------- kernel 2: per-(b,c) top-100 + fused decode + bitmask NMS ----
__global__ void topk_nms_kernel(const float* __restrict__ scores,
                                const float* __restrict__ bboxes,
                                const float* __restrict__ anchors) {
    int c = blockIdx.x, b = blockIdx.y;
    int bc = b * NCLS + c;

    __shared__ ull keys[CAP];
    __shared__ int s_cnt, s_edge;
    __shared__ unsigned hist[512];
    __shared__ float bx[128][4];
    __shared__ float vv[KRET];
    __shared__ unsigned row[KRET][4];
    __shared__ unsigned char keepf[KRET];

    int cnt = g_cnt[bc * CNT_STRIDE];
    if (cnt > CAP) cnt = CAP;
    for (int i = threadIdx.x; i < cnt; i += blockDim.x)
        keys[i] = g_cand[(size_t)bc * CAP + i];
    if (threadIdx.x == 0) {
        s_cnt = cnt;
        g_cnt[bc * CNT_STRIDE] = 0;   // reset for next graph replay
    }
    __syncthreads();

    if (cnt < KRET) {
        // fallback (statistically never on this input, kept for correctness)
        for (int i = threadIdx.x; i < 512; i += blockDim.x) hist[i] = 0;
        __syncthreads();
        const float invw = 512.0f / (THR_HI - SCORE_THR);
        for (int n = threadIdx.x; n < N_ANCH; n += blockDim.x) {
            float s = scores[((size_t)b * N_ANCH + n) * NCLS + c];
            if (s > SCORE_THR && s <= THR_HI) {
                int bin = (int)((s - SCORE_THR) * invw);
                if (bin > 511) bin = 511;
                atomicAdd(&hist[bin], 1u);
            }
        }
        __syncthreads();
        if (threadIdx.x == 0) {
            int need = KRET - cnt;
            unsigned cum = 0; int edge = 0;
            for (int e = 511; e >= 0; --e) {
                cum += hist[e];
                if ((int)cum >= need) { edge = e; break; }
            }
            s_edge = edge;
        }
        __syncthreads();
        int edge = s_edge;
        for (int n = threadIdx.x; n < N_ANCH; n += blockDim.x) {
            float s = scores[((size_t)b * N_ANCH + n) * NCLS + c];
            if (s > SCORE_THR && s <= THR_HI) {
                int bin = (int)((s - SCORE_THR) * invw);
                if (bin > 511) bin = 511;
                if (bin >= edge) {
                    int pos = atomicAdd(&s_cnt, 1);
                    if (pos < CAP)
                        keys[pos] = ((ull)__float_as_uint(s) << 32) |
                                    (unsigned)(~(unsigned)n);
                }
            }
        }
        __syncthreads();
    }

    int M = s_cnt < CAP ? s_cnt : CAP;
    int P = 128; while (P < M) P <<= 1;
    for (int i = threadIdx.x; i < P; i += blockDim.x)
        if (i >= M) keys[i] = 0ull;
    bitonic_desc(keys, P);

    // gather top-100: decode + clip inline (decode kernel eliminated)
    if (threadIdx.x < 128) {
        int k = threadIdx.x;
        if (k < KRET && k < M) {
            ull key = keys[k];
            float s = __uint_as_float((unsigned)(key >> 32));
            unsigned idx = ~(unsigned)(key & 0xFFFFFFFFull);
            vv[k] = s;
            float4 d = ((const float4*)bboxes)[(size_t)b * N_ANCH + idx];
            float4 a = ((const float4*)anchors)[idx];
            float aw = a.z - a.x, ah = a.w - a.y;
            float acx = a.x + 0.5f * aw, acy = a.y + 0.5f * ah;
            float dx = d.x * 0.1f, dy = d.y * 0.1f;
            float dw = fminf(d.z * 0.2f, 4.135f);
            float dh = fminf(d.w * 0.2f, 4.135f);
            float cx = acx + dx * aw, cy = acy + dy * ah;
            float w = aw * expf(dw), h = ah * expf(dh);
            bx[k][0] = fminf(fmaxf(cx - 0.5f * w, 0.0f), 512.0f);
            bx[k][1] = fminf(fmaxf(cy - 0.5f * h, 0.0f), 512.0f);
            bx[k][2] = fminf(fmaxf(cx + 0.5f * w, 0.0f), 512.0f);
            bx[k][3] = fminf(fmaxf(cy + 0.5f * h, 0.0f), 512.0f);
        } else {
            if (k < KRET) vv[k] = -1.0f;
            bx[k][0] = bx[k][1] = bx[k][2] = bx[k][3] = 0.0f;
        }
    }
    __syncthreads();

    // IoU bit-matrix via ballots: warp w covers columns 32w..32w+31
    int wid = threadIdx.x >> 5, lane = threadIdx.x & 31;
    if (wid < 4) {
        int j = threadIdx.x;
        float jx1 = bx[j][0], jy1 = bx[j][1], jx2 = bx[j][2], jy2 = bx[j][3];
        float aj = (jx2 - jx1) * (jy2 - jy1);
        for (int i = 0; i < KRET; ++i) {
            float xx1 = fmaxf(bx[i][0], jx1);
            float yy1 = fmaxf(bx[i][1], jy1);
            float xx2 = fminf(bx[i][2], jx2);
            float yy2 = fminf(bx[i][3], jy2);
            float w = fmaxf(xx2 - xx1, 0.0f);
            float h = fmaxf(yy2 - yy1, 0.0f);
            float inter = w * h;
            float ai = (bx[i][2] - bx[i][0]) * (bx[i][3] - bx[i][1]);
            float iou = inter / (ai + aj - inter + 1e-8f);
            bool pred = (j < KRET) && (j != i) && (iou > IOU_THR);
            unsigned bits = __ballot_sync(0xFFFFFFFFu, pred);
            if (lane == 0) row[i][wid] = bits;
        }
    }
    __syncthreads();

    // serial greedy scan on bitmasks
    if (threadIdx.x == 0) {
        unsigned sup0 = 0, sup1 = 0, sup2 = 0, sup3 = 0;
        for (int i = 0; i < KRET; ++i) {
            unsigned sw = (i < 32) ? sup0 : (i < 64) ? sup1 : (i < 96) ? sup2 : sup3;
            bool keep = !((sw >> (i & 31)) & 1u) && (vv[i] > 0.0f);
            keepf[i] = keep ? 1 : 0;
            if (keep) {
                sup0 |= row[i][0]; sup1 |= row[i][1];
                sup2 |= row[i][2]; sup3 |= row[i][3];
            }
        }
    }
    __syncthreads();

    if (threadIdx.x < KRET) {
        int k = threadIdx.x;
        int base = bc * KRET + k;
        g_cls_scores[base] = keepf[k] ? vv[k] : -1.0f;
        g_cls_boxes[base * 4 + 0] = bx[k][0];
        g_cls_boxes[base * 4 + 1] = bx[k][1];
        g_cls_boxes[base * 4 + 2] = bx[k][2];
        g_cls_boxes[base * 4 + 3] = bx[k][3];
    }
}

// ---------------- kernel 3: merge via histogram selection ----------------
__global__ void merge_kernel(float* __restrict__ out) {
    __shared__ unsigned hist[513];
    __shared__ ull mkeys[MCAP];
    __shared__ int s_cnt, s_edge;
    const int M = NCLS * KRET;
    int b = blockIdx.x;

    for (int i = threadIdx.x; i < 513; i += blockDim.x) hist[i] = 0;
    if (threadIdx.x == 0) s_cnt = 0;
    __syncthreads();

    const float invw = 512.0f / (1.0f - THR_HI);
    for (int i = threadIdx.x; i < M; i += blockDim.x) {
        float s = g_cls_scores[b * M + i];
        if (s > 0.0f) {
            int bin = (s > THR_HI) ? 1 + min(511, (int)((s - THR_HI) * invw)) : 0;
            atomicAdd(&hist[bin], 1u);
        }
    }
    __syncthreads();

    if (threadIdx.x == 0) {
        unsigned cum = 0; int edge = 0;
        for (int e = 512; e >= 0; --e) {
            cum += hist[e];
            if (cum >= KRET) { edge = e; break; }
        }
        s_edge = edge;
    }
    __syncthreads();
    int edge = s_edge;

    for (int i = threadIdx.x; i < M; i += blockDim.x) {
        float s = g_cls_scores[b * M + i];
        if (s > 0.0f) {
            int bin = (s > THR_HI) ? 1 + min(511, (int)((s - THR_HI) * invw)) : 0;
            if (bin >= edge) {
                int pos = atomicAdd(&s_cnt, 1);
                if (pos < MCAP)
                    mkeys[pos] = ((ull)__float_as_uint(s) << 32) |
                                 (unsigned)(~(unsigned)i);
            }
        }
    }
    __syncthreads();

    int cnt = s_cnt < MCAP ? s_cnt : MCAP;
    int P = 128; while (P < cnt) P <<= 1;
    for (int i = threadIdx.x; i < P; i += blockDim.x)
        if (i >= cnt) mkeys[i] = 0ull;
    bitonic_desc(mkeys, P);

    if (threadIdx.x < KRET) {
        int k = threadIdx.x;
        bool valid = (k < cnt);
        float b0 = 0.f, b1 = 0.f, b2 = 0.f, b3 = 0.f;
        float lab = -1.0f, sout = 0.0f;
        if (valid) {
            ull key = mkeys[k];
            float s = __uint_as_float((unsigned)(key >> 32));
            unsigned flat = ~(unsigned)(key & 0xFFFFFFFFull);
            if (s > 0.0f && flat < (unsigned)M) {
                int c = flat / KRET, kk = flat % KRET;
                int base = ((b * NCLS + c) * KRET + kk) * 4;
                b0 = g_cls_boxes[base + 0]; b1 = g_cls_boxes[base + 1];
                b2 = g_cls_boxes[base + 2]; b3 = g_cls_boxes[base + 3];
                lab = (float)c; sout = s;
            }
        }
        int bo = (b * KRET + k) * 4;
        out[bo + 0] = b0; out[bo + 1] = b1; out[bo + 2] = b2; out[bo + 3] = b3;
        out[NB * KRET * 4 + b * KRET + k] = sout;
        out[NB * KRET * 5 + b * KRET + k] = lab;
    }
}

extern "C" void kernel_launch(void* const* d_in, const int* in_sizes, int n_in,
                              void* d_out, int out_size) {
    const float* bboxes  = (const float*)d_in[0];
    const float* scores  = (const float*)d_in[1];
    const float* anchors = (const float*)d_in[2];
    float* out = (float*)d_out;

    // scan: 4 float4 per thread
    unsigned threads_needed = (TOT4 + 3) / 4;
    unsigned grid = (threads_needed + 255) / 256;
    scan_kernel<<<grid, 256>>>(scores);
    topk_nms_kernel<<<dim3(NCLS, NB), 256>>>(scores, bboxes, anchors);
    merge_kernel<<<NB, 1024>>>(out);
}